// round 4
// baseline (speedup 1.0000x reference)
#include <cuda_runtime.h>
#include <cuda_bf16.h>
#include <cstdint>

#define NN 100000      // nodes
#define NE 1600000     // edges
#define DD 32          // feature dim

// ---- scratch (device globals; no allocation allowed) ----------------------
__device__ int   g_deg[NN];
__device__ int   g_tmp[NN];      // per-block exclusive scan
__device__ int   g_blk[128];     // block totals (98 used)
__device__ int   g_blkoff[128];  // block offsets
__device__ int   g_start[NN];
__device__ int   g_cursor[NN];
__device__ unsigned long long g_cv[NE];      // packed (val<<32 | col)
__device__ float g_bufA[NN * DD];
__device__ float g_bufB[NN * DD];

// ---------------------------------------------------------------------------
// 1) zero degree histogram
// ---------------------------------------------------------------------------
__global__ void k_zero(int* __restrict__ deg) {
    int i = blockIdx.x * blockDim.x + threadIdx.x;
    if (i < NN) deg[i] = 0;
}

// ---------------------------------------------------------------------------
// 2) histogram of row degrees
// ---------------------------------------------------------------------------
__global__ void k_hist(const int* __restrict__ erow, int* __restrict__ deg) {
    int e = blockIdx.x * blockDim.x + threadIdx.x;   // grid covers NE exactly
    atomicAdd(&deg[erow[e]], 1);
}

// ---------------------------------------------------------------------------
// 3a) per-block exclusive scan (1024-wide blocks)
// ---------------------------------------------------------------------------
__global__ void k_scan1(const int* __restrict__ deg, int* __restrict__ tmp,
                        int* __restrict__ blk) {
    __shared__ int sh[1024];
    int t = threadIdx.x;
    int i = blockIdx.x * 1024 + t;
    int v = (i < NN) ? deg[i] : 0;
    sh[t] = v;
    __syncthreads();
    for (int off = 1; off < 1024; off <<= 1) {
        int add = (t >= off) ? sh[t - off] : 0;
        __syncthreads();
        sh[t] += add;
        __syncthreads();
    }
    int incl = sh[t];
    if (i < NN) tmp[i] = incl - v;           // exclusive within block
    if (t == 1023) blk[blockIdx.x] = incl;   // block total
}

// ---------------------------------------------------------------------------
// 3b) scan of block totals (single block, 128 threads >= 98 blocks)
// ---------------------------------------------------------------------------
__global__ void k_scan2(const int* __restrict__ blk, int* __restrict__ blkoff,
                        int nblk) {
    __shared__ int sh[128];
    int t = threadIdx.x;
    int v = (t < nblk) ? blk[t] : 0;
    sh[t] = v;
    __syncthreads();
    for (int off = 1; off < 128; off <<= 1) {
        int add = (t >= off) ? sh[t - off] : 0;
        __syncthreads();
        sh[t] += add;
        __syncthreads();
    }
    blkoff[t] = sh[t] - v;                   // exclusive
}

// ---------------------------------------------------------------------------
// 3c) combine: start = cursor = blkoff[b] + tmp
// ---------------------------------------------------------------------------
__global__ void k_scan3(const int* __restrict__ tmp, const int* __restrict__ blkoff,
                        int* __restrict__ start, int* __restrict__ cursor) {
    int i = blockIdx.x * blockDim.x + threadIdx.x;
    if (i < NN) {
        int s = tmp[i] + blkoff[i >> 10];
        start[i]  = s;
        cursor[i] = s;
    }
}

// ---------------------------------------------------------------------------
// 4) scatter edges into CSR slots (packed 8B: val in hi 32, col in lo 32)
// ---------------------------------------------------------------------------
__global__ void k_scatter(const int* __restrict__ erow, const int* __restrict__ ecol,
                          const float* __restrict__ eval,
                          int* __restrict__ cursor, unsigned long long* __restrict__ cv) {
    int e = blockIdx.x * blockDim.x + threadIdx.x;   // grid covers NE exactly
    int r = erow[e];
    int p = atomicAdd(&cursor[r], 1);
    cv[p] = ((unsigned long long)__float_as_uint(eval[e]) << 32) | (unsigned)ecol[e];
}

// ---------------------------------------------------------------------------
// 5) CSR SpMM, warp per row, lane = feature. Fused epilogues:
//    MODE 0: y=acc; out = h_row + acc          (layer 1, h == x)
//    MODE 1: y=acc; out += acc                 (layer 2)
//    MODE 2: out = (out + acc) * 0.25          (layer 3, y not stored)
// ---------------------------------------------------------------------------
template <int MODE>
__global__ void k_spmm_csr(const unsigned long long* __restrict__ cv,
                           const int* __restrict__ start, const int* __restrict__ deg,
                           const float* __restrict__ h, float* __restrict__ ybuf,
                           float* __restrict__ out) {
    int w    = (blockIdx.x * blockDim.x + threadIdx.x) >> 5;   // row
    int lane = threadIdx.x & 31;
    if (w >= NN) return;

    int s = start[w];
    int d = deg[w];
    float acc = 0.f;

    for (int base = 0; base < d; base += 32) {
        int n = min(32, d - base);
        unsigned long long my = 0;
        if (lane < n) my = cv[s + base + lane];

        int j = 0;
        for (; j + 4 <= n; j += 4) {
#pragma unroll
            for (int k = 0; k < 4; k++) {
                unsigned long long e = __shfl_sync(0xffffffffu, my, j + k);
                int   c = (int)(e & 0xffffffffu);
                float v = __uint_as_float((unsigned)(e >> 32));
                acc += v * __ldg(&h[c * DD + lane]);   // 128B coalesced line (L2 hit)
            }
        }
        for (; j < n; j++) {
            unsigned long long e = __shfl_sync(0xffffffffu, my, j);
            int   c = (int)(e & 0xffffffffu);
            float v = __uint_as_float((unsigned)(e >> 32));
            acc += v * __ldg(&h[c * DD + lane]);
        }
    }

    int idx = w * DD + lane;
    if (MODE == 0) {
        ybuf[idx] = acc;
        out[idx]  = h[idx] + acc;
    } else if (MODE == 1) {
        ybuf[idx] = acc;
        out[idx] += acc;
    } else {
        out[idx] = (out[idx] + acc) * 0.25f;
    }
}

extern "C" void kernel_launch(void* const* d_in, const int* in_sizes, int n_in,
                              void* d_out, int out_size) {
    const int*   erow = (const int*)  d_in[0];
    const int*   ecol = (const int*)  d_in[1];
    const float* eval = (const float*)d_in[2];
    const float* x    = (const float*)d_in[3];
    float* out        = (float*)d_out;

    int *deg, *tmp, *blk, *blkoff, *start, *cursor;
    unsigned long long* cv;
    float *bufA, *bufB;
    cudaGetSymbolAddress((void**)&deg,    g_deg);
    cudaGetSymbolAddress((void**)&tmp,    g_tmp);
    cudaGetSymbolAddress((void**)&blk,    g_blk);
    cudaGetSymbolAddress((void**)&blkoff, g_blkoff);
    cudaGetSymbolAddress((void**)&start,  g_start);
    cudaGetSymbolAddress((void**)&cursor, g_cursor);
    cudaGetSymbolAddress((void**)&cv,     g_cv);
    cudaGetSymbolAddress((void**)&bufA,   g_bufA);
    cudaGetSymbolAddress((void**)&bufB,   g_bufB);

    const int nScanBlk = (NN + 1023) / 1024;          // 98
    const int edgeBlks = NE / 256;                    // 6250, exact
    const int nodeBlks = (NN + 255) / 256;            // 391
    const int spmmBlks = (NN + 7) / 8;                // 12500 (8 warps/block)

    // --- build CSR ---
    k_zero<<<nodeBlks, 256>>>(deg);
    k_hist<<<edgeBlks, 256>>>(erow, deg);
    k_scan1<<<nScanBlk, 1024>>>(deg, tmp, blk);
    k_scan2<<<1, 128>>>(blk, blkoff, nScanBlk);
    k_scan3<<<nodeBlks, 256>>>(tmp, blkoff, start, cursor);
    k_scatter<<<edgeBlks, 256>>>(erow, ecol, eval, cursor, cv);

    // --- 3 propagation layers, epilogues fused ---
    k_spmm_csr<0><<<spmmBlks, 256>>>(cv, start, deg, x,    bufA, out);
    k_spmm_csr<1><<<spmmBlks, 256>>>(cv, start, deg, bufA, bufB, out);
    k_spmm_csr<2><<<spmmBlks, 256>>>(cv, start, deg, bufB, bufB, out);
}

// round 9
// speedup vs baseline: 1.1447x; 1.1447x over previous
#include <cuda_runtime.h>
#include <cuda_bf16.h>
#include <cstdint>

#define NN 100000      // nodes
#define NE 1600000     // edges
#define DD 32          // feature dim
#define NC 8           // float4 chunks per node row (DD/4)

// Layer output buffers (device globals; allocation is forbidden).
// float4 typing guarantees 16B alignment for red.v4.
__device__ float4 g_y1[NN * NC];
__device__ float4 g_y2[NN * NC];
__device__ float4 g_y3[NN * NC];

// ---------------------------------------------------------------------------
// zero all three accumulation targets in one pass
// grid is exactly NN*NC threads (800,000 = 3125 * 256)
// ---------------------------------------------------------------------------
__global__ void k_zero3(float4* __restrict__ a, float4* __restrict__ b,
                        float4* __restrict__ c) {
    int i = blockIdx.x * blockDim.x + threadIdx.x;
    const float4 z = make_float4(0.f, 0.f, 0.f, 0.f);
    a[i] = z;
    b[i] = z;
    c[i] = z;
}

// ---------------------------------------------------------------------------
// COO SpMM: y[row[e]] += val[e] * h[col[e]]
// 8 lanes per edge (one float4 chunk each), edge scalars loaded once per
// 8-lane group and shfl-broadcast. Launched with exactly NE*NC threads
// (12.8M = 50,000 * 256): no tail, full warps, full shfl masks.
// ---------------------------------------------------------------------------
__global__ void k_spmm(const int* __restrict__ erow, const int* __restrict__ ecol,
                       const float* __restrict__ eval,
                       const float4* __restrict__ h, float4* __restrict__ y) {
    int t = blockIdx.x * blockDim.x + threadIdx.x;
    int e = t >> 3;            // edge index
    int c = t & 7;             // float4 chunk within the 32-wide feature row
    int lane = threadIdx.x & 31;

    int r = 0, cl = 0; float v = 0.f;
    if ((lane & 7) == 0) {     // one scalar load per 8-lane group
        r  = erow[e];
        cl = ecol[e];
        v  = eval[e];
    }
    unsigned src = lane & ~7u; // broadcast within the group
    r  = __shfl_sync(0xffffffffu, r,  src);
    cl = __shfl_sync(0xffffffffu, cl, src);
    v  = __shfl_sync(0xffffffffu, v,  src);

    float4 hv = h[cl * NC + c];            // coalesced 128B line per edge (L2 hit)
    float4 m = make_float4(v * hv.x, v * hv.y, v * hv.z, v * hv.w);

    float4* dst = &y[r * NC + c];
    asm volatile("red.global.add.v4.f32 [%0], {%1, %2, %3, %4};"
                 :: "l"(dst), "f"(m.x), "f"(m.y), "f"(m.z), "f"(m.w)
                 : "memory");
}

// ---------------------------------------------------------------------------
// final combine: out = 0.25 * (x + y1 + y2 + y3)  (single pass)
// ---------------------------------------------------------------------------
__global__ void k_final(float4* __restrict__ out, const float4* __restrict__ x,
                        const float4* __restrict__ a, const float4* __restrict__ b,
                        const float4* __restrict__ c) {
    int i = blockIdx.x * blockDim.x + threadIdx.x;
    float4 xv = x[i], av = a[i], bv = b[i], cv = c[i];
    out[i] = make_float4((xv.x + av.x + bv.x + cv.x) * 0.25f,
                         (xv.y + av.y + bv.y + cv.y) * 0.25f,
                         (xv.z + av.z + bv.z + cv.z) * 0.25f,
                         (xv.w + av.w + bv.w + cv.w) * 0.25f);
}

extern "C" void kernel_launch(void* const* d_in, const int* in_sizes, int n_in,
                              void* d_out, int out_size) {
    const int*    erow = (const int*)  d_in[0];
    const int*    ecol = (const int*)  d_in[1];
    const float*  eval = (const float*)d_in[2];
    const float4* x    = (const float4*)d_in[3];
    float4* out        = (float4*)d_out;

    float4 *y1, *y2, *y3;
    cudaGetSymbolAddress((void**)&y1, g_y1);
    cudaGetSymbolAddress((void**)&y2, g_y2);
    cudaGetSymbolAddress((void**)&y3, g_y3);

    const int nodeBlocks = (NN * NC) / 256;   // 3125, exact
    const int edgeBlocks = (NE * NC) / 256;   // 50000, exact

    k_zero3<<<nodeBlocks, 256>>>(y1, y2, y3);
    k_spmm <<<edgeBlocks, 256>>>(erow, ecol, eval, x,  y1);   // y1 = A x
    k_spmm <<<edgeBlocks, 256>>>(erow, ecol, eval, y1, y2);   // y2 = A y1
    k_spmm <<<edgeBlocks, 256>>>(erow, ecol, eval, y2, y3);   // y3 = A y2
    k_final<<<nodeBlocks, 256>>>(out, x, y1, y2, y3);         // out = (x+y1+y2+y3)/4
}

// round 10
// speedup vs baseline: 1.2418x; 1.0848x over previous
#include <cuda_runtime.h>
#include <cuda_bf16.h>
#include <cstdint>

#define NN 100000      // nodes
#define NE 1600000     // edges
#define NE2 (NE/2)     // 800000
#define DD 32          // feature dim
#define NC 8           // float4 chunks per node row (DD/4)

// Layer output buffers (device globals; allocation is forbidden).
__device__ float4 g_y1[NN * NC];
__device__ float4 g_y2[NN * NC];
__device__ float4 g_y3[NN * NC];

// ---------------------------------------------------------------------------
// zero all three accumulation targets in one pass (exactly NN*NC threads)
// ---------------------------------------------------------------------------
__global__ void k_zero3(float4* __restrict__ a, float4* __restrict__ b,
                        float4* __restrict__ c) {
    int i = blockIdx.x * blockDim.x + threadIdx.x;
    const float4 z = make_float4(0.f, 0.f, 0.f, 0.f);
    a[i] = z;
    b[i] = z;
    c[i] = z;
}

// ---------------------------------------------------------------------------
// COO SpMM, 2 edges per thread for ILP:
//   thread handles chunk c of edge e and edge e+NE2.
// 8 lanes per edge-chunk-group; scalar loads once per group, shfl-broadcast.
// Grid = NE2*NC threads = 6.4M (25,000 * 256): exact, full warps/masks.
// ---------------------------------------------------------------------------
__global__ void k_spmm(const int* __restrict__ erow, const int* __restrict__ ecol,
                       const float* __restrict__ eval,
                       const float4* __restrict__ h, float4* __restrict__ y) {
    int t = blockIdx.x * blockDim.x + threadIdx.x;
    int e = t >> 3;            // first edge index (0 .. NE2-1)
    int c = t & 7;             // float4 chunk within the 32-float feature row
    int lane = threadIdx.x & 31;

    int r0 = 0, c0 = 0, r1 = 0, c1 = 0;
    float v0 = 0.f, v1 = 0.f;
    if ((lane & 7) == 0) {     // one set of scalar loads per 8-lane group
        r0 = erow[e];        c0 = ecol[e];        v0 = eval[e];
        r1 = erow[e + NE2];  c1 = ecol[e + NE2];  v1 = eval[e + NE2];
    }
    unsigned src = lane & ~7u; // broadcast within the group
    r0 = __shfl_sync(0xffffffffu, r0, src);
    c0 = __shfl_sync(0xffffffffu, c0, src);
    v0 = __shfl_sync(0xffffffffu, v0, src);
    r1 = __shfl_sync(0xffffffffu, r1, src);
    c1 = __shfl_sync(0xffffffffu, c1, src);
    v1 = __shfl_sync(0xffffffffu, v1, src);

    // two independent gathers in flight
    float4 h0 = h[c0 * NC + c];
    float4 h1 = h[c1 * NC + c];

    float4 m0 = make_float4(v0 * h0.x, v0 * h0.y, v0 * h0.z, v0 * h0.w);
    float4 m1 = make_float4(v1 * h1.x, v1 * h1.y, v1 * h1.z, v1 * h1.w);

    float4* d0 = &y[r0 * NC + c];
    float4* d1 = &y[r1 * NC + c];
    asm volatile("red.global.add.v4.f32 [%0], {%1, %2, %3, %4};"
                 :: "l"(d0), "f"(m0.x), "f"(m0.y), "f"(m0.z), "f"(m0.w)
                 : "memory");
    asm volatile("red.global.add.v4.f32 [%0], {%1, %2, %3, %4};"
                 :: "l"(d1), "f"(m1.x), "f"(m1.y), "f"(m1.z), "f"(m1.w)
                 : "memory");
}

// ---------------------------------------------------------------------------
// final combine: out = 0.25 * (x + y1 + y2 + y3)  (single pass)
// ---------------------------------------------------------------------------
__global__ void k_final(float4* __restrict__ out, const float4* __restrict__ x,
                        const float4* __restrict__ a, const float4* __restrict__ b,
                        const float4* __restrict__ c) {
    int i = blockIdx.x * blockDim.x + threadIdx.x;
    float4 xv = x[i], av = a[i], bv = b[i], cv = c[i];
    out[i] = make_float4((xv.x + av.x + bv.x + cv.x) * 0.25f,
                         (xv.y + av.y + bv.y + cv.y) * 0.25f,
                         (xv.z + av.z + bv.z + cv.z) * 0.25f,
                         (xv.w + av.w + bv.w + cv.w) * 0.25f);
}

extern "C" void kernel_launch(void* const* d_in, const int* in_sizes, int n_in,
                              void* d_out, int out_size) {
    const int*    erow = (const int*)  d_in[0];
    const int*    ecol = (const int*)  d_in[1];
    const float*  eval = (const float*)d_in[2];
    const float4* x    = (const float4*)d_in[3];
    float4* out        = (float4*)d_out;

    float4 *y1, *y2, *y3;
    cudaGetSymbolAddress((void**)&y1, g_y1);
    cudaGetSymbolAddress((void**)&y2, g_y2);
    cudaGetSymbolAddress((void**)&y3, g_y3);

    const int nodeBlocks = (NN * NC) / 256;    // 3125, exact
    const int edgeBlocks = (NE2 * NC) / 256;   // 25000, exact

    k_zero3<<<nodeBlocks, 256>>>(y1, y2, y3);
    k_spmm <<<edgeBlocks, 256>>>(erow, ecol, eval, x,  y1);   // y1 = A x
    k_spmm <<<edgeBlocks, 256>>>(erow, ecol, eval, y1, y2);   // y2 = A y1
    k_spmm <<<edgeBlocks, 256>>>(erow, ecol, eval, y2, y3);   // y3 = A y2
    k_final<<<nodeBlocks, 256>>>(out, x, y1, y2, y3);         // out = (x+y1+y2+y3)/4
}

// round 12
// speedup vs baseline: 1.2618x; 1.0161x over previous
#include <cuda_runtime.h>
#include <cuda_bf16.h>
#include <cstdint>

#define NN 100000      // nodes
#define NE 1600000     // edges
#define NE4 (NE/4)     // 400000
#define DD 32          // feature dim
#define NC 8           // float4 chunks per node row (DD/4)

// Layer output buffers (device globals; allocation is forbidden).
__device__ float4 g_y1[NN * NC];
__device__ float4 g_y2[NN * NC];
__device__ float4 g_y3[NN * NC];

// ---------------------------------------------------------------------------
// zero all three accumulation targets in one pass (exactly NN*NC threads)
// ---------------------------------------------------------------------------
__global__ void k_zero3(float4* __restrict__ a, float4* __restrict__ b,
                        float4* __restrict__ c) {
    int i = blockIdx.x * blockDim.x + threadIdx.x;
    const float4 z = make_float4(0.f, 0.f, 0.f, 0.f);
    a[i] = z;
    b[i] = z;
    c[i] = z;
}

// ---------------------------------------------------------------------------
// COO SpMM, 4 edges per thread for ILP:
//   thread handles chunk c of edges e, e+NE4, e+2*NE4, e+3*NE4.
// 8 lanes per edge-chunk-group; scalar loads once per group, shfl-broadcast.
// Grid = NE4*NC threads = 3.2M (12,500 * 256): exact, full warps/masks.
// ---------------------------------------------------------------------------
__global__ void k_spmm(const int* __restrict__ erow, const int* __restrict__ ecol,
                       const float* __restrict__ eval,
                       const float4* __restrict__ h, float4* __restrict__ y) {
    int t = blockIdx.x * blockDim.x + threadIdx.x;
    int e = t >> 3;            // base edge index (0 .. NE4-1)
    int c = t & 7;             // float4 chunk within the 32-float feature row
    int lane = threadIdx.x & 31;

    int r[4], cl[4];
    float v[4];
#pragma unroll
    for (int k = 0; k < 4; k++) { r[k] = 0; cl[k] = 0; v[k] = 0.f; }

    if ((lane & 7) == 0) {     // one set of scalar loads per 8-lane group
#pragma unroll
        for (int k = 0; k < 4; k++) {
            int ee = e + k * NE4;
            r[k]  = erow[ee];
            cl[k] = ecol[ee];
            v[k]  = eval[ee];
        }
    }
    unsigned src = lane & ~7u; // broadcast within the group
#pragma unroll
    for (int k = 0; k < 4; k++) {
        r[k]  = __shfl_sync(0xffffffffu, r[k],  src);
        cl[k] = __shfl_sync(0xffffffffu, cl[k], src);
        v[k]  = __shfl_sync(0xffffffffu, v[k],  src);
    }

    // four independent gathers in flight
    float4 hv[4];
#pragma unroll
    for (int k = 0; k < 4; k++) hv[k] = h[cl[k] * NC + c];

#pragma unroll
    for (int k = 0; k < 4; k++) {
        float4 m = make_float4(v[k] * hv[k].x, v[k] * hv[k].y,
                               v[k] * hv[k].z, v[k] * hv[k].w);
        float4* dst = &y[r[k] * NC + c];
        asm volatile("red.global.add.v4.f32 [%0], {%1, %2, %3, %4};"
                     :: "l"(dst), "f"(m.x), "f"(m.y), "f"(m.z), "f"(m.w)
                     : "memory");
    }
}

// ---------------------------------------------------------------------------
// final combine: out = 0.25 * (x + y1 + y2 + y3)  (single pass)
// ---------------------------------------------------------------------------
__global__ void k_final(float4* __restrict__ out, const float4* __restrict__ x,
                        const float4* __restrict__ a, const float4* __restrict__ b,
                        const float4* __restrict__ c) {
    int i = blockIdx.x * blockDim.x + threadIdx.x;
    float4 xv = x[i], av = a[i], bv = b[i], cv = c[i];
    out[i] = make_float4((xv.x + av.x + bv.x + cv.x) * 0.25f,
                         (xv.y + av.y + bv.y + cv.y) * 0.25f,
                         (xv.z + av.z + bv.z + cv.z) * 0.25f,
                         (xv.w + av.w + bv.w + cv.w) * 0.25f);
}

extern "C" void kernel_launch(void* const* d_in, const int* in_sizes, int n_in,
                              void* d_out, int out_size) {
    const int*    erow = (const int*)  d_in[0];
    const int*    ecol = (const int*)  d_in[1];
    const float*  eval = (const float*)d_in[2];
    const float4* x    = (const float4*)d_in[3];
    float4* out        = (float4*)d_out;

    float4 *y1, *y2, *y3;
    cudaGetSymbolAddress((void**)&y1, g_y1);
    cudaGetSymbolAddress((void**)&y2, g_y2);
    cudaGetSymbolAddress((void**)&y3, g_y3);

    const int nodeBlocks = (NN * NC) / 256;    // 3125, exact
    const int edgeBlocks = (NE4 * NC) / 256;   // 12500, exact

    k_zero3<<<nodeBlocks, 256>>>(y1, y2, y3);
    k_spmm <<<edgeBlocks, 256>>>(erow, ecol, eval, x,  y1);   // y1 = A x
    k_spmm <<<edgeBlocks, 256>>>(erow, ecol, eval, y1, y2);   // y2 = A y1
    k_spmm <<<edgeBlocks, 256>>>(erow, ecol, eval, y2, y3);   // y3 = A y2
    k_final<<<nodeBlocks, 256>>>(out, x, y1, y2, y3);         // out = (x+y1+y2+y3)/4
}